// round 15
// baseline (speedup 1.0000x reference)
#include <cuda_runtime.h>
#include <stdint.h>
#include <math_constants.h>

// QueryDepthPoint: depth-constrained radius search.  B=8, N=16384, M=2048,
// NSAMPLE=64, DIS_Z=0.5.  Output (solved R12): f32 buffer, idx (B,M,64) at
// [0,1048576), pts_cnt (B,M) at [1048576,1064960).
//
// R13: chunk prefilter 27.1us. R14: finer chunks/blocks NEUTRAL -> tail is
// bound by serial cost per genuinely-matching chunk, not prefilter skips.
// R15: float4 (LDG.128) + element-order 128-wide compaction (one branch per
// 128 elems) + next-chunk prefetch to hide L1 latency in the serial chain.

#define QB 8
#define QN 16384
#define QM 2048
#define QNS 64
#define QDIS_Z 0.5f
#define CHUNK 128
#define NCHUNK (QN / CHUNK)            // 128 chunks per batch row

__device__ float2 g_bounds[QB * NCHUNK];   // [b][chunk] = (min, max) of z1

__global__ void __launch_bounds__(256)
bounds_kernel(const float* __restrict__ xyz1)
{
    const int warp = (blockIdx.x * blockDim.x + threadIdx.x) >> 5;  // 0..1023
    const int lane = threadIdx.x & 31;
    if (warp >= QB * NCHUNK) return;
    const int b = warp >> 7;
    const int chunk = warp & (NCHUNK - 1);
    const float* __restrict__ z1 = xyz1 + b * 3 * QN + 2 * QN + chunk * CHUNK;

    float mn =  CUDART_INF_F, mx = -CUDART_INF_F;
    #pragma unroll
    for (int i = 0; i < 4; i++) {
        float v = z1[i * 32 + lane];
        mn = fminf(mn, v);
        mx = fmaxf(mx, v);
    }
    #pragma unroll
    for (int off = 16; off; off >>= 1) {
        mn = fminf(mn, __shfl_xor_sync(0xFFFFFFFFu, mn, off));
        mx = fmaxf(mx, __shfl_xor_sync(0xFFFFFFFFu, mx, off));
    }
    if (lane == 0)
        g_bounds[b * NCHUNK + chunk] = make_float2(mn, mx);
}

__global__ void __launch_bounds__(128)
qdp_kernel(const float* __restrict__ xyz1, int n1,
           const float* __restrict__ xyz2, int n2,
           float* __restrict__ idx_out,
           float* __restrict__ cnt_out)
{
    const int warp_id = (blockIdx.x * blockDim.x + threadIdx.x) >> 5;
    const int lane = threadIdx.x & 31;
    if (warp_id >= QB * QM) return;
    const int b = warp_id / QM;
    const int m = warp_id - b * QM;

    const int z1_base = b * 3 * QN + 2 * QN;
    const float* __restrict__ z1 =
        (z1_base + QN <= n1) ? (xyz1 + z1_base) : xyz1;
    int z2_i = b * 3 * QM + 2 * QM + m;
    if (z2_i >= n2) z2_i = (n2 > 0) ? (n2 - 1) : 0;
    const float z2v = __ldg(&xyz2[z2_i]);

    float* __restrict__ out = idx_out + warp_id * QNS;

    const unsigned full = 0xFFFFFFFFu;
    const unsigned lt_mask = (lane == 0) ? 0u : (0xFFFFFFFFu >> (32 - lane));

    // ---- Candidate-chunk mask: 4 ballots cover 128 chunks of 128 ----
    // Widened by 5e-4 so (v - z2) rounding can never cause a false skip.
    const float2* __restrict__ bnd = g_bounds + b * NCHUNK;
    const float lo = z2v - (QDIS_Z + 5e-4f);
    const float hi = z2v + (QDIS_Z + 5e-4f);
    unsigned long long c01, c23;
    {
        float2 b0 = bnd[lane];
        float2 b1 = bnd[32 + lane];
        float2 b2 = bnd[64 + lane];
        float2 b3 = bnd[96 + lane];
        unsigned w0 = __ballot_sync(full, (b0.x < hi) && (b0.y > lo));
        unsigned w1 = __ballot_sync(full, (b1.x < hi) && (b1.y > lo));
        unsigned w2 = __ballot_sync(full, (b2.x < hi) && (b2.y > lo));
        unsigned w3 = __ballot_sync(full, (b3.x < hi) && (b3.y > lo));
        c01 = (unsigned long long)w0 | ((unsigned long long)w1 << 32);
        c23 = (unsigned long long)w2 | ((unsigned long long)w3 << 32);
    }

    int cnt = 0;          // warp-uniform
    int firstj = 0;       // warp-uniform

    // Candidate iterator over two 64-bit words (ascending chunk order).
    #define NEXT_CHUNK(dst)                                             \
        do {                                                            \
            if (c01) { int _k = __ffsll(c01) - 1; c01 &= c01 - 1;       \
                       (dst) = _k; }                                    \
            else if (c23) { int _k = __ffsll(c23) - 1; c23 &= c23 - 1;  \
                       (dst) = 64 + _k; }                               \
            else (dst) = -1;                                            \
        } while (0)

    int cur;
    NEXT_CHUNK(cur);
    float4 vcur = make_float4(0.f, 0.f, 0.f, 0.f);
    if (cur >= 0)
        vcur = __ldg((const float4*)(z1 + cur * CHUNK) + lane);

    while (cur >= 0) {                       // warp-uniform loop
        int nxt;
        NEXT_CHUNK(nxt);
        float4 vnxt = vcur;
        if (nxt >= 0)                        // prefetch next candidate chunk
            vnxt = __ldg((const float4*)(z1 + nxt * CHUNK) + lane);

        // ---- process current chunk: 128 elements, element order j0+4l+s ----
        const int j0 = cur * CHUNK;
        unsigned m4 = (fabsf(vcur.x - z2v) < QDIS_Z ? 1u : 0u)
                    | (fabsf(vcur.y - z2v) < QDIS_Z ? 2u : 0u)
                    | (fabsf(vcur.z - z2v) < QDIS_Z ? 4u : 0u)
                    | (fabsf(vcur.w - z2v) < QDIS_Z ? 8u : 0u);
        unsigned B0 = __ballot_sync(full, m4 & 1u);
        unsigned B1 = __ballot_sync(full, m4 & 2u);
        unsigned B2 = __ballot_sync(full, m4 & 4u);
        unsigned B3 = __ballot_sync(full, m4 & 8u);

        if (B0 | B1 | B2 | B3) {             // warp-uniform
            // elements before (lane, s): all matches at lanes < lane (any s),
            // then own sub-elements s' < s sequentially below.
            int p = cnt + __popc(B0 & lt_mask) + __popc(B1 & lt_mask)
                        + __popc(B2 & lt_mask) + __popc(B3 & lt_mask);
            const int j = j0 + 4 * lane;
            if (m4 & 1u) { if (p < QNS) out[p] = (float)(j    ); p++; }
            if (m4 & 2u) { if (p < QNS) out[p] = (float)(j + 1); p++; }
            if (m4 & 4u) { if (p < QNS) out[p] = (float)(j + 2); p++; }
            if (m4 & 8u) { if (p < QNS) out[p] = (float)(j + 3); p++; }

            if (cnt == 0) {                  // first match index (min 4l+s)
                int best = 1 << 30;
                if (B0) best = min(best, 4 * (__ffs(B0) - 1));
                if (B1) best = min(best, 4 * (__ffs(B1) - 1) + 1);
                if (B2) best = min(best, 4 * (__ffs(B2) - 1) + 2);
                if (B3) best = min(best, 4 * (__ffs(B3) - 1) + 3);
                firstj = j0 + best;
            }
            cnt += __popc(B0) + __popc(B1) + __popc(B2) + __popc(B3);
            if (cnt >= QNS) break;           // warp-uniform early exit
        }
        cur = nxt;
        vcur = vnxt;
    }
    #undef NEXT_CHUNK

    if (cnt > QNS) cnt = QNS;
    const float fillv = (cnt > 0) ? (float)firstj : 0.0f;
    for (int s = cnt + lane; s < QNS; s += 32)
        out[s] = fillv;
    if (lane == 0)
        cnt_out[warp_id] = (float)cnt;
}

extern "C" void kernel_launch(void* const* d_in, const int* in_sizes, int n_in,
                              void* d_out, int out_size) {
    const int E1 = QB * 3 * QN;   // 393216 elements (xyz1)
    const int E2 = QB * 3 * QM;   // 49152 elements (xyz2)

    const float* xyz1 = nullptr;
    const float* xyz2 = nullptr;
    for (int i = 0; i < n_in; i++) {
        const int sz = in_sizes[i];
        if ((sz == E1 || sz == E1 * 4) && !xyz1) xyz1 = (const float*)d_in[i];
        else if ((sz == E2 || sz == E2 * 4) && !xyz2) xyz2 = (const float*)d_in[i];
    }
    if ((!xyz1 || !xyz2) && n_in >= 2) {
        if (in_sizes[0] >= in_sizes[1]) {
            if (!xyz1) xyz1 = (const float*)d_in[0];
            if (!xyz2) xyz2 = (const float*)d_in[1];
        } else {
            if (!xyz1) xyz1 = (const float*)d_in[1];
            if (!xyz2) xyz2 = (const float*)d_in[0];
        }
    }
    if (!xyz1 && n_in >= 1) xyz1 = (const float*)d_in[0];
    if (!xyz2) xyz2 = xyz1;

    float* idx_out = (float*)d_out;                  // [0, 1048576)
    float* cnt_out = (float*)d_out + QB * QM * QNS;  // [1048576, 1064960)

    // Kernel 1: per-128-chunk z1 bounds (1024 warps).
    bounds_kernel<<<(QB * NCHUNK * 32 + 255) / 256, 256>>>(xyz1);

    // Kernel 2: query scan (float4 + prefetch), 4-warp blocks.
    const int total_warps = QB * QM;                 // 16384
    const int threads = 128;
    const int blocks = (total_warps * 32 + threads - 1) / threads;   // 4096
    qdp_kernel<<<blocks, threads>>>(xyz1, E1, xyz2, E2, idx_out, cnt_out);
}